// round 13
// baseline (speedup 1.0000x reference)
#include <cuda_runtime.h>
#include <cuda_bf16.h>
#include <cstdint>

#define NN 32768
#define FD 128
#define NE 262144
#define NL 64

// ---------------- scratch ----------------
__device__ float g_hw[NN * FD];                 // gemm output (fp32), agg input
__device__ __nv_bfloat16 g_ah[NN * FD];         // agg output split: hi
__device__ __nv_bfloat16 g_al[NN * FD];         // agg output split: lo
__device__ float g_dinv[NN];
__device__ float g_selfw[NN];
__device__ __align__(16) int g_cnt[NN];
__device__ int   g_cur[NN];
__device__ __align__(16) int g_row[NN + 4];
__device__ int   g_src[NE];
__device__ int   g_dst[NE];
__device__ int2  g_edge[NE];                    // {src, weight bits}
__device__ int   g_is64;
__device__ __nv_bfloat16 g_wh[NL * 16384];      // [l][n_perm][k] transposed+row-permuted
__device__ __nv_bfloat16 g_wl[NL * 16384];

// ---------------- helpers ----------------
__device__ __forceinline__ uint32_t smem_u32(const void* p) {
    uint32_t a;
    asm("{ .reg .u64 t; cvta.to.shared.u64 t, %1; cvt.u32.u64 %0, t; }"
        : "=r"(a) : "l"(p));
    return a;
}
__device__ __forceinline__ void ldm_x4(uint32_t* r, uint32_t addr) {
    asm volatile("ldmatrix.sync.aligned.m8n8.x4.shared.b16 {%0,%1,%2,%3}, [%4];"
                 : "=r"(r[0]), "=r"(r[1]), "=r"(r[2]), "=r"(r[3]) : "r"(addr));
}
__device__ __forceinline__ void mma16816(float* c, const uint32_t* a,
                                         uint32_t b0, uint32_t b1) {
    asm volatile(
        "mma.sync.aligned.m16n8k16.row.col.f32.bf16.bf16.f32 "
        "{%0,%1,%2,%3}, {%4,%5,%6,%7}, {%8,%9}, {%0,%1,%2,%3};"
        : "+f"(c[0]), "+f"(c[1]), "+f"(c[2]), "+f"(c[3])
        : "r"(a[0]), "r"(a[1]), "r"(a[2]), "r"(a[3]), "r"(b0), "r"(b1));
}
// split float4 -> packed bf16x2 hi (h01,h23) and lo (l01,l23)
__device__ __forceinline__ void split4(float4 a, uint32_t& h01, uint32_t& h23,
                                       uint32_t& l01, uint32_t& l23) {
    asm("cvt.rn.bf16x2.f32 %0, %1, %2;" : "=r"(h01) : "f"(a.y), "f"(a.x));
    asm("cvt.rn.bf16x2.f32 %0, %1, %2;" : "=r"(h23) : "f"(a.w), "f"(a.z));
    float hx = __uint_as_float(h01 << 16);
    float hy = __uint_as_float(h01 & 0xffff0000u);
    float hz = __uint_as_float(h23 << 16);
    float hw_ = __uint_as_float(h23 & 0xffff0000u);
    asm("cvt.rn.bf16x2.f32 %0, %1, %2;" : "=r"(l01) : "f"(a.y - hy), "f"(a.x - hx));
    asm("cvt.rn.bf16x2.f32 %0, %1, %2;" : "=r"(l23) : "f"(a.w - hw_), "f"(a.z - hz));
}

// ---------------- setup kernels ----------------
__global__ void detect_kernel(const int* __restrict__ ei) {
    if (threadIdx.x == 0 && blockIdx.x == 0) {
        int odd_zero = 1;
        for (int i = 0; i < 64; i++)
            if (ei[2 * i + 1] != 0) { odd_zero = 0; break; }
        g_is64 = odd_zero;
    }
}
__global__ void zero_kernel() {
    int i = blockIdx.x * blockDim.x + threadIdx.x;
    if (i < NN) { g_cnt[i] = 0; g_cur[i] = 0; }
}
__global__ void convert_count_kernel(const int* __restrict__ ei) {
    int e = blockIdx.x * blockDim.x + threadIdx.x;
    if (e >= NE) return;
    int s, d;
    if (g_is64) {
        const long long* p = (const long long*)ei;
        s = (int)p[e];
        d = (int)p[NE + e];
    } else {
        s = ei[e];
        d = ei[NE + e];
    }
    g_src[e] = s;
    g_dst[e] = d;
    atomicAdd(&g_cnt[d], 1);
}
__global__ void scan_kernel() {
    __shared__ int sh[1024];
    int t = threadIdx.x;
    const int4* cnt4 = (const int4*)g_cnt;
    int4 c[8];
    int s = 0;
#pragma unroll
    for (int i = 0; i < 8; i++) {
        c[i] = cnt4[t * 8 + i];
        s += c[i].x + c[i].y + c[i].z + c[i].w;
    }
    sh[t] = s;
    __syncthreads();
    for (int off = 1; off < 1024; off <<= 1) {
        int v = (t >= off) ? sh[t - off] : 0;
        __syncthreads();
        sh[t] += v;
        __syncthreads();
    }
    int run = (t == 0) ? 0 : sh[t - 1];
    int4* row4 = (int4*)g_row;
#pragma unroll
    for (int i = 0; i < 8; i++) {
        int4 v;
        v.x = run; run += c[i].x;
        v.y = run; run += c[i].y;
        v.z = run; run += c[i].z;
        v.w = run; run += c[i].w;
        row4[t * 8 + i] = v;
    }
    if (t == 1023) g_row[NN] = run;
}
__global__ void dinv_kernel() {
    int v = blockIdx.x * blockDim.x + threadIdx.x;
    if (v >= NN) return;
    float deg = (float)(g_cnt[v] + 1);
    float di = 1.0f / sqrtf(deg);
    g_dinv[v] = di;
    g_selfw[v] = di * di;
}
__global__ void scatter_kernel() {
    int e = blockIdx.x * blockDim.x + threadIdx.x;
    if (e >= NE) return;
    int s = g_src[e];
    int d = g_dst[e];
    int pos = g_row[d] + atomicAdd(&g_cur[d], 1);
    g_edge[pos] = make_int2(s, __float_as_int(g_dinv[s] * g_dinv[d]));
}
// W split + transpose + n-row permutation j(n): storage row n holds logical
// column j(n) = [p(3)|q(2)|s(1)|b(1)] for n = [p(3)|s(1)|q(2)|b(1)].
// This makes each thread's MMA fragment land on 4 contiguous logical columns.
__global__ void wsplit_kernel(const float* __restrict__ wts) {
    int idx = blockIdx.x * blockDim.x + threadIdx.x;
    if (idx >= NL * 16384) return;
    int l = idx >> 14;
    int e = idx & 16383;
    int k = e >> 7;
    int n = e & 127;    // storage row
    int jn = (n & 0x71) | ((n & 6) << 1) | ((n >> 3) & 1) << 1;
    // decompose carefully: n = p*16 + s*8 + q*2 + b  -> j = p*16 + q*4 + s*2 + b
    {
        int p = n >> 4, s = (n >> 3) & 1, q = (n >> 1) & 3, b = n & 1;
        jn = p * 16 + q * 4 + s * 2 + b;
    }
    float v = wts[(l << 14) + (k << 7) + jn];
    __nv_bfloat16 hi = __float2bfloat16(v);
    float hf = __bfloat162float(hi);
    __nv_bfloat16 lo = __float2bfloat16(v - hf);
    int o = (l << 14) + n * 128 + k;
    g_wh[o] = hi;
    g_wl[o] = lo;
}
// split x into g_ah/g_al (layer-0 GEMM input)
__global__ void x0split_kernel(const float* __restrict__ x) {
    int i = blockIdx.x * blockDim.x + threadIdx.x;   // float4 index
    if (i >= NN * 32) return;
    float4 v = ((const float4*)x)[i];
    uint32_t h01, h23, l01, l23;
    split4(v, h01, h23, l01, l23);
    ((uint2*)g_ah)[i] = make_uint2(h01, h23);
    ((uint2*)g_al)[i] = make_uint2(l01, l23);
}

// ---------------- GEMM: g_hw = split(A) @ W, both tiles, ks-outer ----------------
#define PITCH 136
#define TILE_BYTES (128 * PITCH * 2)
#define OFF_WH  0
#define OFF_WL  (TILE_BYTES)
#define OFF_A0H (2 * TILE_BYTES)
#define OFF_A0L (3 * TILE_BYTES)
#define OFF_A1H (4 * TILE_BYTES)
#define OFF_A1L (5 * TILE_BYTES)
#define SM_SZ   (6 * TILE_BYTES)

__global__ void __launch_bounds__(256) gemm_kernel(int layer) {
    extern __shared__ char sm[];
    uint32_t sbase = smem_u32(sm);

    int t = threadIdx.x;
    int w = t >> 5;
    int lane = t & 31;

    // --- stage W hi/lo ---
    {
        const uint4* wh4 = (const uint4*)(g_wh + ((size_t)layer << 14));
        const uint4* wl4 = (const uint4*)(g_wl + ((size_t)layer << 14));
        __nv_bfloat16* sWh = (__nv_bfloat16*)(sm + OFF_WH);
        __nv_bfloat16* sWl = (__nv_bfloat16*)(sm + OFF_WL);
#pragma unroll
        for (int i = 0; i < 8; i++) {
            int idx8 = t + i * 256;
            int n = idx8 >> 4;
            int k8 = (idx8 & 15) << 3;
            *(uint4*)&sWh[n * PITCH + k8] = wh4[idx8];
            *(uint4*)&sWl[n * PITCH + k8] = wl4[idx8];
        }
    }

    int wrow = w * 16;
    // --- stage A (both tiles, hi+lo): pure copies, warp-private rows ---
    {
        const uint4* ah4 = (const uint4*)g_ah;
        const uint4* al4 = (const uint4*)g_al;
        int k8 = lane & 15;            // uint4 within row
        int rh = lane >> 4;            // row half
#pragma unroll
        for (int tile = 0; tile < 2; tile++) {
            int tb = blockIdx.x * 256 + tile * 128;
            char* dH = sm + (tile ? OFF_A1H : OFF_A0H);
            char* dL = sm + (tile ? OFF_A1L : OFF_A0L);
#pragma unroll
            for (int i = 0; i < 8; i++) {
                int r = wrow + i * 2 + rh;
                size_t gi = (size_t)(tb + r) * 16 + k8;
                *(uint4*)(dH + r * (PITCH * 2) + k8 * 16) = ah4[gi];
                *(uint4*)(dL + r * (PITCH * 2) + k8 * 16) = al4[gi];
            }
        }
    }
    __syncthreads();

    int g = lane >> 2;
    int q = lane & 3;
    uint32_t aRowOff = (uint32_t)((wrow + (lane & 15)) * (PITCH * 2) +
                                  ((lane >> 4) * 8) * 2);
    uint32_t addrA0h = sbase + OFF_A0H + aRowOff;
    uint32_t addrA0l = sbase + OFF_A0L + aRowOff;
    uint32_t addrA1h = sbase + OFF_A1H + aRowOff;
    uint32_t addrA1l = sbase + OFF_A1L + aRowOff;
    uint32_t bLaneOff = (uint32_t)((((lane & 7) + ((lane >> 4) << 3)) * PITCH) * 2 +
                                   ((lane >> 3) & 1) * 16);
    uint32_t addrBh = sbase + OFF_WH + bLaneOff;
    uint32_t addrBl = sbase + OFF_WL + bLaneOff;

    float acc0[16][4], acc1[16][4];
#pragma unroll
    for (int i = 0; i < 16; i++)
#pragma unroll
        for (int j = 0; j < 4; j++) { acc0[i][j] = 0.0f; acc1[i][j] = 0.0f; }

#pragma unroll
    for (int ks = 0; ks < 8; ks++) {
        uint32_t a0h[4], a0l[4], a1h[4], a1l[4];
        ldm_x4(a0h, addrA0h + ks * 32);
        ldm_x4(a0l, addrA0l + ks * 32);
        ldm_x4(a1h, addrA1h + ks * 32);
        ldm_x4(a1l, addrA1l + ks * 32);
#pragma unroll
        for (int p = 0; p < 8; p++) {
            uint32_t bh[4], bl[4];
            uint32_t boff = (uint32_t)(p * (16 * PITCH * 2) + ks * 32);
            ldm_x4(bh, addrBh + boff);
            ldm_x4(bl, addrBl + boff);
            int n0 = p * 2, n1 = n0 + 1;
            mma16816(acc0[n0], a0h, bh[0], bh[1]);
            mma16816(acc0[n1], a0h, bh[2], bh[3]);
            mma16816(acc1[n0], a1h, bh[0], bh[1]);
            mma16816(acc1[n1], a1h, bh[2], bh[3]);
            mma16816(acc0[n0], a0h, bl[0], bl[1]);
            mma16816(acc0[n1], a0h, bl[2], bl[3]);
            mma16816(acc1[n0], a1h, bl[0], bl[1]);
            mma16816(acc1[n1], a1h, bl[2], bl[3]);
            mma16816(acc0[n0], a0l, bh[0], bh[1]);
            mma16816(acc0[n1], a0l, bh[2], bh[3]);
            mma16816(acc1[n0], a1l, bh[0], bh[1]);
            mma16816(acc1[n1], a1l, bh[2], bh[3]);
        }
    }

    // ---- epilogue: with W-row permutation, fragments land contiguous ----
    {
        int tb0 = blockIdx.x * 256;
#pragma unroll
        for (int p = 0; p < 8; p++) {
            int col = p * 16 + q * 4;
            int n0 = p * 2, n1 = n0 + 1;
            int r0 = tb0 + wrow + g;
            *(float4*)&g_hw[(size_t)r0 * 128 + col] =
                make_float4(acc0[n0][0], acc0[n0][1], acc0[n1][0], acc0[n1][1]);
            *(float4*)&g_hw[(size_t)(r0 + 8) * 128 + col] =
                make_float4(acc0[n0][2], acc0[n0][3], acc0[n1][2], acc0[n1][3]);
            int r1 = tb0 + 128 + wrow + g;
            *(float4*)&g_hw[(size_t)r1 * 128 + col] =
                make_float4(acc1[n0][0], acc1[n0][1], acc1[n1][0], acc1[n1][1]);
            *(float4*)&g_hw[(size_t)(r1 + 8) * 128 + col] =
                make_float4(acc1[n0][2], acc1[n0][3], acc1[n1][2], acc1[n1][3]);
        }
    }
}

// ---------------- aggregation: writes bf16 hi/lo split directly ----------------
__global__ void __launch_bounds__(256) agg_kernel(const float* __restrict__ bias) {
    int w = (blockIdx.x * blockDim.x + threadIdx.x) >> 5;
    int lane = threadIdx.x & 31;
    if (w >= NN) return;

    const float4* __restrict__ hw4 = (const float4*)g_hw;

    float sw = g_selfw[w];
    float4 v = hw4[(size_t)w * 32 + lane];
    float4 acc = make_float4(sw * v.x, sw * v.y, sw * v.z, sw * v.w);

    int beg = g_row[w];
    int end = g_row[w + 1];
    for (int e = beg; e < end; e++) {
        int2 ed = g_edge[e];
        float wt = __int_as_float(ed.y);
        float4 u = hw4[(size_t)ed.x * 32 + lane];
        acc.x += wt * u.x;
        acc.y += wt * u.y;
        acc.z += wt * u.z;
        acc.w += wt * u.w;
    }
    float4 b = ((const float4*)bias)[lane];
    acc.x = fmaxf(acc.x + b.x, 0.0f);
    acc.y = fmaxf(acc.y + b.y, 0.0f);
    acc.z = fmaxf(acc.z + b.z, 0.0f);
    acc.w = fmaxf(acc.w + b.w, 0.0f);

    uint32_t h01, h23, l01, l23;
    split4(acc, h01, h23, l01, l23);
    ((uint2*)g_ah)[(size_t)w * 32 + lane] = make_uint2(h01, h23);
    ((uint2*)g_al)[(size_t)w * 32 + lane] = make_uint2(l01, l23);
}

// ---------------- final: h = hi+lo (agg63 output); out = (h + x) @ cls_w + cls_b ----------------
__global__ void __launch_bounds__(256) final_kernel(const float* __restrict__ x,
                                                    const float* __restrict__ cw,
                                                    const float* __restrict__ cb,
                                                    float* __restrict__ out) {
    int node = (blockIdx.x * blockDim.x + threadIdx.x) >> 5;
    int lane = threadIdx.x & 31;
    if (node >= NN) return;

    uint2 hb = ((const uint2*)g_ah)[(size_t)node * 32 + lane];
    uint2 lb = ((const uint2*)g_al)[(size_t)node * 32 + lane];
    float4 xv = ((const float4*)x)[(size_t)node * 32 + lane];
    float4 hv;
    hv.x = __uint_as_float(hb.x << 16) + __uint_as_float(lb.x << 16) + xv.x;
    hv.y = __uint_as_float(hb.x & 0xffff0000u) + __uint_as_float(lb.x & 0xffff0000u) + xv.y;
    hv.z = __uint_as_float(hb.y << 16) + __uint_as_float(lb.y << 16) + xv.z;
    hv.w = __uint_as_float(hb.y & 0xffff0000u) + __uint_as_float(lb.y & 0xffff0000u) + xv.w;

    const float4* w4 = (const float4*)cw;
    int f0 = lane * 4;
    float4 w0 = w4[f0], w1 = w4[f0 + 1], w2 = w4[f0 + 2], w3 = w4[f0 + 3];
    float4 p;
    p.x = hv.x * w0.x + hv.y * w1.x + hv.z * w2.x + hv.w * w3.x;
    p.y = hv.x * w0.y + hv.y * w1.y + hv.z * w2.y + hv.w * w3.y;
    p.z = hv.x * w0.z + hv.y * w1.z + hv.z * w2.z + hv.w * w3.z;
    p.w = hv.x * w0.w + hv.y * w1.w + hv.z * w2.w + hv.w * w3.w;

#pragma unroll
    for (int off = 16; off; off >>= 1) {
        p.x += __shfl_xor_sync(0xffffffffu, p.x, off);
        p.y += __shfl_xor_sync(0xffffffffu, p.y, off);
        p.z += __shfl_xor_sync(0xffffffffu, p.z, off);
        p.w += __shfl_xor_sync(0xffffffffu, p.w, off);
    }
    if (lane == 0) {
        float4 b = *(const float4*)cb;
        p.x += b.x; p.y += b.y; p.z += b.z; p.w += b.w;
        ((float4*)out)[node] = p;
    }
}

// ---------------- launch ----------------
extern "C" void kernel_launch(void* const* d_in, const int* in_sizes, int n_in,
                              void* d_out, int out_size) {
    const float* x      = (const float*)d_in[0];
    const int*   ei     = (const int*)d_in[1];
    const float* wts    = (const float*)d_in[2];
    const float* biases = (const float*)d_in[3];
    const float* cls_w  = (const float*)d_in[4];
    const float* cls_b  = (const float*)d_in[5];
    float* out = (float*)d_out;

    cudaFuncSetAttribute(gemm_kernel, cudaFuncAttributeMaxDynamicSharedMemorySize,
                         SM_SZ);

    detect_kernel<<<1, 32>>>(ei);
    zero_kernel<<<NN / 256, 256>>>();
    convert_count_kernel<<<NE / 256, 256>>>(ei);
    scan_kernel<<<1, 1024>>>();
    dinv_kernel<<<NN / 256, 256>>>();
    scatter_kernel<<<NE / 256, 256>>>();
    wsplit_kernel<<<NL * 16384 / 256, 256>>>(wts);
    x0split_kernel<<<NN * 32 / 256, 256>>>(x);

    for (int l = 0; l < NL; l++) {
        gemm_kernel<<<128, 256, SM_SZ>>>(l);
        agg_kernel<<<NN / 8, 256>>>(biases + (size_t)l * 128);
    }
    final_kernel<<<NN / 8, 256>>>(x, cls_w, cls_b, out);
}

// round 14
// speedup vs baseline: 1.4792x; 1.4792x over previous
#include <cuda_runtime.h>
#include <cuda_bf16.h>
#include <cstdint>

#define NN 32768
#define FD 128
#define NE 262144
#define NL 64

// ---------------- scratch ----------------
__device__ float g_hw[NN * FD];                 // gemm output (fp32), agg input
__device__ __nv_bfloat16 g_ah[NN * FD];         // agg output split: hi
__device__ __nv_bfloat16 g_al[NN * FD];         // agg output split: lo
__device__ float g_dinv[NN];
__device__ float g_selfw[NN];
__device__ __align__(16) int g_cnt[NN];
__device__ int   g_cur[NN];
__device__ __align__(16) int g_row[NN + 4];
__device__ int   g_src[NE];
__device__ int   g_dst[NE];
__device__ int2  g_edge[NE];                    // {src, weight bits}
__device__ int   g_is64;
__device__ __nv_bfloat16 g_wh[NL * 16384];      // [l][n][k] transposed
__device__ __nv_bfloat16 g_wl[NL * 16384];

// ---------------- helpers ----------------
__device__ __forceinline__ uint32_t smem_u32(const void* p) {
    uint32_t a;
    asm("{ .reg .u64 t; cvta.to.shared.u64 t, %1; cvt.u32.u64 %0, t; }"
        : "=r"(a) : "l"(p));
    return a;
}
__device__ __forceinline__ void ldm_x4(uint32_t* r, uint32_t addr) {
    asm volatile("ldmatrix.sync.aligned.m8n8.x4.shared.b16 {%0,%1,%2,%3}, [%4];"
                 : "=r"(r[0]), "=r"(r[1]), "=r"(r[2]), "=r"(r[3]) : "r"(addr));
}
__device__ __forceinline__ void mma16816(float* c, const uint32_t* a,
                                         uint32_t b0, uint32_t b1) {
    asm volatile(
        "mma.sync.aligned.m16n8k16.row.col.f32.bf16.bf16.f32 "
        "{%0,%1,%2,%3}, {%4,%5,%6,%7}, {%8,%9}, {%0,%1,%2,%3};"
        : "+f"(c[0]), "+f"(c[1]), "+f"(c[2]), "+f"(c[3])
        : "r"(a[0]), "r"(a[1]), "r"(a[2]), "r"(a[3]), "r"(b0), "r"(b1));
}
// split float4 -> packed bf16x2 hi (h01,h23) and lo (l01,l23)
__device__ __forceinline__ void split4(float4 a, uint32_t& h01, uint32_t& h23,
                                       uint32_t& l01, uint32_t& l23) {
    asm("cvt.rn.bf16x2.f32 %0, %1, %2;" : "=r"(h01) : "f"(a.y), "f"(a.x));
    asm("cvt.rn.bf16x2.f32 %0, %1, %2;" : "=r"(h23) : "f"(a.w), "f"(a.z));
    float hx = __uint_as_float(h01 << 16);
    float hy = __uint_as_float(h01 & 0xffff0000u);
    float hz = __uint_as_float(h23 << 16);
    float hw_ = __uint_as_float(h23 & 0xffff0000u);
    asm("cvt.rn.bf16x2.f32 %0, %1, %2;" : "=r"(l01) : "f"(a.y - hy), "f"(a.x - hx));
    asm("cvt.rn.bf16x2.f32 %0, %1, %2;" : "=r"(l23) : "f"(a.w - hw_), "f"(a.z - hz));
}

// ---------------- setup kernels ----------------
__global__ void detect_kernel(const int* __restrict__ ei) {
    if (threadIdx.x == 0 && blockIdx.x == 0) {
        int odd_zero = 1;
        for (int i = 0; i < 64; i++)
            if (ei[2 * i + 1] != 0) { odd_zero = 0; break; }
        g_is64 = odd_zero;
    }
}
__global__ void zero_kernel() {
    int i = blockIdx.x * blockDim.x + threadIdx.x;
    if (i < NN) { g_cnt[i] = 0; g_cur[i] = 0; }
}
__global__ void convert_count_kernel(const int* __restrict__ ei) {
    int e = blockIdx.x * blockDim.x + threadIdx.x;
    if (e >= NE) return;
    int s, d;
    if (g_is64) {
        const long long* p = (const long long*)ei;
        s = (int)p[e];
        d = (int)p[NE + e];
    } else {
        s = ei[e];
        d = ei[NE + e];
    }
    g_src[e] = s;
    g_dst[e] = d;
    atomicAdd(&g_cnt[d], 1);
}
__global__ void scan_kernel() {
    __shared__ int sh[1024];
    int t = threadIdx.x;
    const int4* cnt4 = (const int4*)g_cnt;
    int4 c[8];
    int s = 0;
#pragma unroll
    for (int i = 0; i < 8; i++) {
        c[i] = cnt4[t * 8 + i];
        s += c[i].x + c[i].y + c[i].z + c[i].w;
    }
    sh[t] = s;
    __syncthreads();
    for (int off = 1; off < 1024; off <<= 1) {
        int v = (t >= off) ? sh[t - off] : 0;
        __syncthreads();
        sh[t] += v;
        __syncthreads();
    }
    int run = (t == 0) ? 0 : sh[t - 1];
    int4* row4 = (int4*)g_row;
#pragma unroll
    for (int i = 0; i < 8; i++) {
        int4 v;
        v.x = run; run += c[i].x;
        v.y = run; run += c[i].y;
        v.z = run; run += c[i].z;
        v.w = run; run += c[i].w;
        row4[t * 8 + i] = v;
    }
    if (t == 1023) g_row[NN] = run;
}
__global__ void dinv_kernel() {
    int v = blockIdx.x * blockDim.x + threadIdx.x;
    if (v >= NN) return;
    float deg = (float)(g_cnt[v] + 1);
    float di = 1.0f / sqrtf(deg);
    g_dinv[v] = di;
    g_selfw[v] = di * di;
}
__global__ void scatter_kernel() {
    int e = blockIdx.x * blockDim.x + threadIdx.x;
    if (e >= NE) return;
    int s = g_src[e];
    int d = g_dst[e];
    int pos = g_row[d] + atomicAdd(&g_cur[d], 1);
    g_edge[pos] = make_int2(s, __float_as_int(g_dinv[s] * g_dinv[d]));
}
// W split + transpose (no permutation): g_wh[l][n][k] = hi(W[l][k][n])
__global__ void wsplit_kernel(const float* __restrict__ wts) {
    int idx = blockIdx.x * blockDim.x + threadIdx.x;
    if (idx >= NL * 16384) return;
    int l = idx >> 14;
    int e = idx & 16383;
    int k = e >> 7;
    int n = e & 127;
    float v = wts[idx];
    __nv_bfloat16 hi = __float2bfloat16(v);
    float hf = __bfloat162float(hi);
    __nv_bfloat16 lo = __float2bfloat16(v - hf);
    int o = (l << 14) + n * 128 + k;
    g_wh[o] = hi;
    g_wl[o] = lo;
}
// split x into g_ah/g_al (layer-0 GEMM input)
__global__ void x0split_kernel(const float* __restrict__ x) {
    int i = blockIdx.x * blockDim.x + threadIdx.x;   // float4 index
    if (i >= NN * 32) return;
    float4 v = ((const float4*)x)[i];
    uint32_t h01, h23, l01, l23;
    split4(v, h01, h23, l01, l23);
    ((uint2*)g_ah)[i] = make_uint2(h01, h23);
    ((uint2*)g_al)[i] = make_uint2(l01, l23);
}

// ---------------- GEMM: g_hw = split(A) @ W, both tiles, ks-outer ----------------
#define PITCH 136
#define TILE_BYTES (128 * PITCH * 2)
#define OFF_WH  0
#define OFF_WL  (TILE_BYTES)
#define OFF_A0H (2 * TILE_BYTES)
#define OFF_A0L (3 * TILE_BYTES)
#define OFF_A1H (4 * TILE_BYTES)
#define OFF_A1L (5 * TILE_BYTES)
#define SM_SZ   (6 * TILE_BYTES)

__global__ void __launch_bounds__(256) gemm_kernel(int layer) {
    extern __shared__ char sm[];
    uint32_t sbase = smem_u32(sm);

    int t = threadIdx.x;
    int w = t >> 5;
    int lane = t & 31;

    // --- stage W hi/lo ---
    {
        const uint4* wh4 = (const uint4*)(g_wh + ((size_t)layer << 14));
        const uint4* wl4 = (const uint4*)(g_wl + ((size_t)layer << 14));
        __nv_bfloat16* sWh = (__nv_bfloat16*)(sm + OFF_WH);
        __nv_bfloat16* sWl = (__nv_bfloat16*)(sm + OFF_WL);
#pragma unroll
        for (int i = 0; i < 8; i++) {
            int idx8 = t + i * 256;
            int n = idx8 >> 4;
            int k8 = (idx8 & 15) << 3;
            *(uint4*)&sWh[n * PITCH + k8] = wh4[idx8];
            *(uint4*)&sWl[n * PITCH + k8] = wl4[idx8];
        }
    }

    int wrow = w * 16;
    // --- stage A (both tiles, hi+lo): pure copies, warp-private rows ---
    {
        const uint4* ah4 = (const uint4*)g_ah;
        const uint4* al4 = (const uint4*)g_al;
        int k8 = lane & 15;            // uint4 within row
        int rh = lane >> 4;            // row half
#pragma unroll
        for (int tile = 0; tile < 2; tile++) {
            int tb = blockIdx.x * 256 + tile * 128;
            char* dH = sm + (tile ? OFF_A1H : OFF_A0H);
            char* dL = sm + (tile ? OFF_A1L : OFF_A0L);
#pragma unroll
            for (int i = 0; i < 8; i++) {
                int r = wrow + i * 2 + rh;
                size_t gi = (size_t)(tb + r) * 16 + k8;
                *(uint4*)(dH + r * (PITCH * 2) + k8 * 16) = ah4[gi];
                *(uint4*)(dL + r * (PITCH * 2) + k8 * 16) = al4[gi];
            }
        }
    }
    __syncthreads();

    int g = lane >> 2;
    int q = lane & 3;
    uint32_t aRowOff = (uint32_t)((wrow + (lane & 15)) * (PITCH * 2) +
                                  ((lane >> 4) * 8) * 2);
    uint32_t addrA0h = sbase + OFF_A0H + aRowOff;
    uint32_t addrA0l = sbase + OFF_A0L + aRowOff;
    uint32_t addrA1h = sbase + OFF_A1H + aRowOff;
    uint32_t addrA1l = sbase + OFF_A1L + aRowOff;
    uint32_t bLaneOff = (uint32_t)((((lane & 7) + ((lane >> 4) << 3)) * PITCH) * 2 +
                                   ((lane >> 3) & 1) * 16);
    uint32_t addrBh = sbase + OFF_WH + bLaneOff;
    uint32_t addrBl = sbase + OFF_WL + bLaneOff;

    float acc0[16][4], acc1[16][4];
#pragma unroll
    for (int i = 0; i < 16; i++)
#pragma unroll
        for (int j = 0; j < 4; j++) { acc0[i][j] = 0.0f; acc1[i][j] = 0.0f; }

#pragma unroll
    for (int ks = 0; ks < 8; ks++) {
        uint32_t a0h[4], a0l[4], a1h[4], a1l[4];
        ldm_x4(a0h, addrA0h + ks * 32);
        ldm_x4(a0l, addrA0l + ks * 32);
        ldm_x4(a1h, addrA1h + ks * 32);
        ldm_x4(a1l, addrA1l + ks * 32);
#pragma unroll
        for (int p = 0; p < 8; p++) {
            uint32_t bh[4], bl[4];
            uint32_t boff = (uint32_t)(p * (16 * PITCH * 2) + ks * 32);
            ldm_x4(bh, addrBh + boff);
            ldm_x4(bl, addrBl + boff);
            int n0 = p * 2, n1 = n0 + 1;
            mma16816(acc0[n0], a0h, bh[0], bh[1]);
            mma16816(acc0[n1], a0h, bh[2], bh[3]);
            mma16816(acc1[n0], a1h, bh[0], bh[1]);
            mma16816(acc1[n1], a1h, bh[2], bh[3]);
            mma16816(acc0[n0], a0h, bl[0], bl[1]);
            mma16816(acc0[n1], a0h, bl[2], bl[3]);
            mma16816(acc1[n0], a1h, bl[0], bl[1]);
            mma16816(acc1[n1], a1h, bl[2], bl[3]);
            mma16816(acc0[n0], a0l, bh[0], bh[1]);
            mma16816(acc0[n1], a0l, bh[2], bh[3]);
            mma16816(acc1[n0], a1l, bh[0], bh[1]);
            mma16816(acc1[n1], a1l, bh[2], bh[3]);
        }
    }

    // ---- epilogue: float2 stores (natural MMA register pairs, no extra pressure) ----
    {
        int tb0 = blockIdx.x * 256;
#pragma unroll
        for (int nt = 0; nt < 16; nt++) {
            int col = nt * 8 + q * 2;
            int r0 = tb0 + wrow + g;
            *(float2*)&g_hw[(size_t)r0 * 128 + col] =
                make_float2(acc0[nt][0], acc0[nt][1]);
            *(float2*)&g_hw[(size_t)(r0 + 8) * 128 + col] =
                make_float2(acc0[nt][2], acc0[nt][3]);
            int r1 = tb0 + 128 + wrow + g;
            *(float2*)&g_hw[(size_t)r1 * 128 + col] =
                make_float2(acc1[nt][0], acc1[nt][1]);
            *(float2*)&g_hw[(size_t)(r1 + 8) * 128 + col] =
                make_float2(acc1[nt][2], acc1[nt][3]);
        }
    }
}

// ---------------- aggregation: writes bf16 hi/lo split directly ----------------
__global__ void __launch_bounds__(256) agg_kernel(const float* __restrict__ bias) {
    int w = (blockIdx.x * blockDim.x + threadIdx.x) >> 5;
    int lane = threadIdx.x & 31;
    if (w >= NN) return;

    const float4* __restrict__ hw4 = (const float4*)g_hw;

    float sw = g_selfw[w];
    float4 v = hw4[(size_t)w * 32 + lane];
    float4 acc = make_float4(sw * v.x, sw * v.y, sw * v.z, sw * v.w);

    int beg = g_row[w];
    int end = g_row[w + 1];
    for (int e = beg; e < end; e++) {
        int2 ed = g_edge[e];
        float wt = __int_as_float(ed.y);
        float4 u = hw4[(size_t)ed.x * 32 + lane];
        acc.x += wt * u.x;
        acc.y += wt * u.y;
        acc.z += wt * u.z;
        acc.w += wt * u.w;
    }
    float4 b = ((const float4*)bias)[lane];
    acc.x = fmaxf(acc.x + b.x, 0.0f);
    acc.y = fmaxf(acc.y + b.y, 0.0f);
    acc.z = fmaxf(acc.z + b.z, 0.0f);
    acc.w = fmaxf(acc.w + b.w, 0.0f);

    uint32_t h01, h23, l01, l23;
    split4(acc, h01, h23, l01, l23);
    ((uint2*)g_ah)[(size_t)w * 32 + lane] = make_uint2(h01, h23);
    ((uint2*)g_al)[(size_t)w * 32 + lane] = make_uint2(l01, l23);
}

// ---------------- final: h = hi+lo (agg63 output); out = (h + x) @ cls_w + cls_b ----------------
__global__ void __launch_bounds__(256) final_kernel(const float* __restrict__ x,
                                                    const float* __restrict__ cw,
                                                    const float* __restrict__ cb,
                                                    float* __restrict__ out) {
    int node = (blockIdx.x * blockDim.x + threadIdx.x) >> 5;
    int lane = threadIdx.x & 31;
    if (node >= NN) return;

    uint2 hb = ((const uint2*)g_ah)[(size_t)node * 32 + lane];
    uint2 lb = ((const uint2*)g_al)[(size_t)node * 32 + lane];
    float4 xv = ((const float4*)x)[(size_t)node * 32 + lane];
    float4 hv;
    hv.x = __uint_as_float(hb.x << 16) + __uint_as_float(lb.x << 16) + xv.x;
    hv.y = __uint_as_float(hb.x & 0xffff0000u) + __uint_as_float(lb.x & 0xffff0000u) + xv.y;
    hv.z = __uint_as_float(hb.y << 16) + __uint_as_float(lb.y << 16) + xv.z;
    hv.w = __uint_as_float(hb.y & 0xffff0000u) + __uint_as_float(lb.y & 0xffff0000u) + xv.w;

    const float4* w4 = (const float4*)cw;
    int f0 = lane * 4;
    float4 w0 = w4[f0], w1 = w4[f0 + 1], w2 = w4[f0 + 2], w3 = w4[f0 + 3];
    float4 p;
    p.x = hv.x * w0.x + hv.y * w1.x + hv.z * w2.x + hv.w * w3.x;
    p.y = hv.x * w0.y + hv.y * w1.y + hv.z * w2.y + hv.w * w3.y;
    p.z = hv.x * w0.z + hv.y * w1.z + hv.z * w2.z + hv.w * w3.z;
    p.w = hv.x * w0.w + hv.y * w1.w + hv.z * w2.w + hv.w * w3.w;

#pragma unroll
    for (int off = 16; off; off >>= 1) {
        p.x += __shfl_xor_sync(0xffffffffu, p.x, off);
        p.y += __shfl_xor_sync(0xffffffffu, p.y, off);
        p.z += __shfl_xor_sync(0xffffffffu, p.z, off);
        p.w += __shfl_xor_sync(0xffffffffu, p.w, off);
    }
    if (lane == 0) {
        float4 b = *(const float4*)cb;
        p.x += b.x; p.y += b.y; p.z += b.z; p.w += b.w;
        ((float4*)out)[node] = p;
    }
}

// ---------------- launch ----------------
extern "C" void kernel_launch(void* const* d_in, const int* in_sizes, int n_in,
                              void* d_out, int out_size) {
    const float* x      = (const float*)d_in[0];
    const int*   ei     = (const int*)d_in[1];
    const float* wts    = (const float*)d_in[2];
    const float* biases = (const float*)d_in[3];
    const float* cls_w  = (const float*)d_in[4];
    const float* cls_b  = (const float*)d_in[5];
    float* out = (float*)d_out;

    cudaFuncSetAttribute(gemm_kernel, cudaFuncAttributeMaxDynamicSharedMemorySize,
                         SM_SZ);

    detect_kernel<<<1, 32>>>(ei);
    zero_kernel<<<NN / 256, 256>>>();
    convert_count_kernel<<<NE / 256, 256>>>(ei);
    scan_kernel<<<1, 1024>>>();
    dinv_kernel<<<NN / 256, 256>>>();
    scatter_kernel<<<NE / 256, 256>>>();
    wsplit_kernel<<<NL * 16384 / 256, 256>>>(wts);
    x0split_kernel<<<NN * 32 / 256, 256>>>(x);

    for (int l = 0; l < NL; l++) {
        gemm_kernel<<<128, 256, SM_SZ>>>(l);
        agg_kernel<<<NN / 8, 256>>>(biases + (size_t)l * 128);
    }
    final_kernel<<<NN / 8, 256>>>(x, cls_w, cls_b, out);
}